// round 7
// baseline (speedup 1.0000x reference)
#include <cuda_runtime.h>
#include <math.h>
#include <stdint.h>

// Problem constants
#define BATCH 8
#define SEQ   2048
#define FEAT  1024
#define KD    512
#define VD    512
#define OUTD  1536   // FEAT + VD

// Scratch (device globals; no allocations allowed)
__device__ float g_q[BATCH * SEQ * KD];
__device__ float g_k[BATCH * SEQ * KD];
__device__ float g_v[BATCH * SEQ * VD];
__device__ float g_logits[BATCH * SEQ * SEQ];   // probs, unnormalized
__device__ float g_rsum[BATCH * SEQ];           // 1/rowsum for PV epilogue

// 3-stage smem: per stage, A = 128x32 words (16KB) + B = 4096 words (16KB)
#define STAGE_WORDS 8192
#define SMEM_BYTES  (3 * STAGE_WORDS * 4)       // 96 KB

__device__ __forceinline__ void cp16(uint32_t* dst, const void* src) {
    uint32_t a = (uint32_t)__cvta_generic_to_shared(dst);
    asm volatile("cp.async.cg.shared.global [%0], [%1], 16;\n" :: "r"(a), "l"(src));
}
__device__ __forceinline__ void cp_commit() {
    asm volatile("cp.async.commit_group;\n" ::: "memory");
}
__device__ __forceinline__ void cp_wait1() {
    asm volatile("cp.async.wait_group 1;\n" ::: "memory");
}

// ---------------------------------------------------------------------------
// Tensor-core GEMM (mma m16n8k8 tf32, raw fp32 bits = RZ truncation)
// CTA tile 128x128, BK=32, 3-stage cp.async pipeline, XOR-swizzled smem,
// one __syncthreads per k-iteration, intra-iter fragment double-buffering,
// 2 CTAs/SM.
// MODE 0: fused QKV projection. NN. blockIdx.z in {0,1,2} selects (B,bias,C).
// MODE 1: QK^T. NT. 1D triangular grid (136 lower-tri tiles).
// MODE 2: PV.  NN, causal K clamp, rowscale epilogue, + x-copy into out.
// ---------------------------------------------------------------------------
template<int MODE>
__global__ __launch_bounds__(256, 2) void mma_gemm(
    const float* __restrict__ A,
    const float* __restrict__ B,
    const float* __restrict__ bias,
    const float* __restrict__ rowscale,
    float* __restrict__ C,
    int lda, int ldb, int ldc, int K,
    long long sA, long long sB, long long sC,
    float alpha,
    const float* __restrict__ B1, const float* __restrict__ B2,
    const float* __restrict__ bias1, const float* __restrict__ bias2,
    float* __restrict__ C1, float* __restrict__ C2)
{
    constexpr bool BT       = (MODE == 1);
    constexpr bool CAUSAL_K = (MODE == 2);

    int m0, n0;
    if (MODE == 1) {
        const int t = blockIdx.x;
        int i = (int)((sqrtf(8.0f * (float)t + 1.0f) - 1.0f) * 0.5f);
        if ((i + 1) * (i + 2) / 2 <= t) i++;
        if (i * (i + 1) / 2 > t) i--;
        const int j = t - i * (i + 1) / 2;
        m0 = i * 128;
        n0 = j * 128;
    } else {
        m0 = blockIdx.y * 128;
        n0 = blockIdx.x * 128;
    }

    const int z = blockIdx.z;
    if (MODE == 0) {
        if (z == 1) { B = B1; bias = bias1; C = C1; }
        else if (z == 2) { B = B2; bias = bias2; C = C2; }
    } else {
        A += (long long)z * sA;
        B += (long long)z * sB;
        C += (long long)z * sC;
        if (MODE == 2) rowscale += (long long)z * SEQ;
    }

    const int K_end = CAUSAL_K ? (K < m0 + 128 ? K : m0 + 128) : K;
    const int n_iter = K_end >> 5;

    extern __shared__ uint32_t smem[];

    const int tid  = threadIdx.x;
    const int lane = tid & 31;
    const int w    = tid >> 5;
    const int wm   = w & 1;       // 0..1
    const int wn   = w >> 1;      // 0..3
    const int l4   = lane >> 2;   // 0..7
    const int lm   = lane & 3;    // 0..3

    // XOR-swizzled staging:
    //   A / B-NT: word (r,c) -> r*32 + (c ^ ((r&7)<<2))
    //   B-NN:     word (k,n) -> k*128 + (n ^ ((k&3)<<3))
    auto load_tile = [&](int k0, int s) {
        uint32_t* Sa = smem + s * STAGE_WORDS;
        uint32_t* Sb = Sa + 4096;
        #pragma unroll
        for (int i = 0; i < 4; i++) {
            const int idx = tid + i * 256;
            const int r   = idx >> 3;
            const int c4  = (idx & 7) << 2;
            cp16(&Sa[r * 32 + (c4 ^ ((r & 7) << 2))],
                 &A[(long long)(m0 + r) * lda + k0 + c4]);
        }
        if (BT) {
            #pragma unroll
            for (int i = 0; i < 4; i++) {
                const int idx = tid + i * 256;
                const int r   = idx >> 3;
                const int c4  = (idx & 7) << 2;
                cp16(&Sb[r * 32 + (c4 ^ ((r & 7) << 2))],
                     &B[(long long)(n0 + r) * ldb + k0 + c4]);
            }
        } else {
            #pragma unroll
            for (int i = 0; i < 4; i++) {
                const int idx = tid + i * 256;
                const int kk  = idx >> 5;
                const int n4  = (idx & 31) << 2;
                cp16(&Sb[kk * 128 + (n4 ^ ((kk & 3) << 3))],
                     &B[(long long)(k0 + kk) * ldb + n0 + n4]);
            }
        }
    };

    float acc[4][4][4];
    #pragma unroll
    for (int i = 0; i < 4; i++)
        #pragma unroll
        for (int j = 0; j < 4; j++)
            #pragma unroll
            for (int r = 0; r < 4; r++) acc[i][j][r] = 0.0f;

    // prologue: stages 0 and 1 in flight
    load_tile(0, 0);
    cp_commit();
    if (1 < n_iter) load_tile(32, 1);
    cp_commit();

    int s = 0;        // compute stage
    int ls = 2;       // next load stage
    for (int it = 0; it < n_iter; it++) {
        cp_wait1();           // group `it` complete (committed 2 iters ago)
        __syncthreads();      // WAR: everyone done with buffer (it-1)%3

        if (it + 2 < n_iter) load_tile((it + 2) << 5, ls);
        cp_commit();          // keep group numbering iteration-aligned

        const uint32_t* Sa = smem + s * STAGE_WORDS;
        const uint32_t* Sb = Sa + 4096;

        // fragment loader for one ks step
        auto load_frags = [&](int kk, uint32_t (&a)[4][4], uint32_t (&b)[4][2]) {
            #pragma unroll
            for (int tm = 0; tm < 4; tm++) {
                const int r0 = wm * 64 + tm * 16 + l4;
                const int c0 = (kk + lm) ^ (l4 << 2);
                const int c1 = (kk + lm + 4) ^ (l4 << 2);
                a[tm][0] = Sa[r0 * 32 + c0];
                a[tm][1] = Sa[(r0 + 8) * 32 + c0];
                a[tm][2] = Sa[r0 * 32 + c1];
                a[tm][3] = Sa[(r0 + 8) * 32 + c1];
            }
            #pragma unroll
            for (int tn = 0; tn < 4; tn++) {
                if (BT) {
                    const int rb = wn * 32 + tn * 8 + l4;
                    b[tn][0] = Sb[rb * 32 + ((kk + lm) ^ (l4 << 2))];
                    b[tn][1] = Sb[rb * 32 + ((kk + lm + 4) ^ (l4 << 2))];
                } else {
                    const int col = (wn * 32 + tn * 8 + l4) ^ (lm << 3);
                    b[tn][0] = Sb[(kk + lm) * 128 + col];
                    b[tn][1] = Sb[(kk + lm + 4) * 128 + col];
                }
            }
        };

        // intra-iter double-buffered ks pipeline
        uint32_t aF[2][4][4];
        uint32_t bF[2][4][2];
        load_frags(0, aF[0], bF[0]);
        #pragma unroll
        for (int ks = 0; ks < 4; ks++) {
            const int cur = ks & 1;
            if (ks < 3) load_frags((ks + 1) * 8, aF[cur ^ 1], bF[cur ^ 1]);
            #pragma unroll
            for (int tm = 0; tm < 4; tm++)
                #pragma unroll
                for (int tn = 0; tn < 4; tn++) {
                    asm volatile(
                        "mma.sync.aligned.m16n8k8.row.col.f32.tf32.tf32.f32 "
                        "{%0,%1,%2,%3}, {%4,%5,%6,%7}, {%8,%9}, {%0,%1,%2,%3};\n"
                        : "+f"(acc[tm][tn][0]), "+f"(acc[tm][tn][1]),
                          "+f"(acc[tm][tn][2]), "+f"(acc[tm][tn][3])
                        : "r"(aF[cur][tm][0]), "r"(aF[cur][tm][1]),
                          "r"(aF[cur][tm][2]), "r"(aF[cur][tm][3]),
                          "r"(bF[cur][tn][0]), "r"(bF[cur][tn][1]));
                }
        }
        s  = (s  == 2) ? 0 : s + 1;
        ls = (ls == 2) ? 0 : ls + 1;
    }

    // ---- epilogue ----
    #pragma unroll
    for (int tm = 0; tm < 4; tm++) {
        const int row = m0 + wm * 64 + tm * 16 + l4;
        float f0 = alpha, f1 = alpha;
        if (MODE == 2) { f0 = alpha * rowscale[row]; f1 = alpha * rowscale[row + 8]; }
        #pragma unroll
        for (int tn = 0; tn < 4; tn++) {
            const int col = n0 + wn * 32 + tn * 8 + (lm << 1);
            float bx = 0.0f, by = 0.0f;
            if (MODE == 0) { bx = bias[col]; by = bias[col + 1]; }
            float2 v0, v1;
            v0.x = acc[tm][tn][0] * f0 + bx;
            v0.y = acc[tm][tn][1] * f0 + by;
            v1.x = acc[tm][tn][2] * f1 + bx;
            v1.y = acc[tm][tn][3] * f1 + by;
            *(float2*)&C[(long long)row * ldc + col]       = v0;
            *(float2*)&C[(long long)(row + 8) * ldc + col] = v1;
        }
    }

    // ---- MODE 2: fold x-copy into PV (this CTA's 128x256 x block) ----
    if (MODE == 2) {
        // B1 = x (as floats), C - FEAT = out base row pointer region
        const float4* x4 = (const float4*)B1;   // [BATCH*SEQ, 256] float4
        float4* o4 = (float4*)(C - FEAT);       // rows of OUTD floats = 384 float4
        const int xc0 = (int)blockIdx.x * 64;   // float4 col offset in x
        #pragma unroll 4
        for (int i = tid; i < 128 * 64; i += 256) {
            const int r  = i >> 6;
            const int c4 = i & 63;
            const long long grow = (long long)z * SEQ + m0 + r;
            o4[(long long)(m0 + r) * 384 + xc0 + c4] = x4[grow * 256 + xc0 + c4];
        }
    }
}

// ---------------------------------------------------------------------------
// Warp-per-row softmax (unnormalized): p[i]=exp(p[i]-max); rsum=1/sum.
// Zeros the band tail [q+1, ceil128(q+1)) that PV's clamped K-loop touches.
// ---------------------------------------------------------------------------
__global__ __launch_bounds__(256) void softmax_kernel(float* __restrict__ logits,
                                                      float* __restrict__ rsum)
{
    const int wid  = threadIdx.x >> 5;
    const int lane = threadIdx.x & 31;
    const long long row = (long long)blockIdx.x * 8 + wid;
    const int q = (int)(row % SEQ);
    float* p = logits + row * SEQ;
    const int len  = q + 1;
    const int len4 = len >> 2;
    const int band = ((q >> 7) + 1) << 7;
    float4* p4 = (float4*)p;

    float mx = -INFINITY;
    for (int i = lane; i < len4; i += 32) {
        float4 v = p4[i];
        mx = fmaxf(mx, fmaxf(fmaxf(v.x, v.y), fmaxf(v.z, v.w)));
    }
    for (int i = (len4 << 2) + lane; i < len; i += 32) mx = fmaxf(mx, p[i]);
    #pragma unroll
    for (int o = 16; o > 0; o >>= 1)
        mx = fmaxf(mx, __shfl_xor_sync(0xffffffffu, mx, o));

    float sum = 0.0f;
    for (int i = lane; i < len4; i += 32) {
        float4 v = p4[i];
        v.x = __expf(v.x - mx);
        v.y = __expf(v.y - mx);
        v.z = __expf(v.z - mx);
        v.w = __expf(v.w - mx);
        p4[i] = v;
        sum += (v.x + v.y) + (v.z + v.w);
    }
    for (int i = (len4 << 2) + lane; i < len; i += 32) {
        float e = __expf(p[i] - mx);
        p[i] = e;
        sum += e;
    }
    #pragma unroll
    for (int o = 16; o > 0; o >>= 1)
        sum += __shfl_xor_sync(0xffffffffu, sum, o);

    if (lane == 0) rsum[row] = 1.0f / sum;

    // zero band tail (len..band); len may be unaligned — scalar head, f4 body
    int i = len + lane;
    for (; i < band && (i & 3); i += 32) { }    // alignment handled below
    for (i = len + lane; i < band; i += 32) p[i] = 0.0f;
}

// ---------------------------------------------------------------------------
extern "C" void kernel_launch(void* const* d_in, const int* in_sizes, int n_in,
                              void* d_out, int out_size)
{
    const float* x  = (const float*)d_in[0];
    const float* Wq = (const float*)d_in[1];
    const float* bq = (const float*)d_in[2];
    const float* Wk = (const float*)d_in[3];
    const float* bk = (const float*)d_in[4];
    const float* Wv = (const float*)d_in[5];
    const float* bv = (const float*)d_in[6];
    float* out = (float*)d_out;

    float *q, *k, *v, *logits, *rsum;
    cudaGetSymbolAddress((void**)&q,      g_q);
    cudaGetSymbolAddress((void**)&k,      g_k);
    cudaGetSymbolAddress((void**)&v,      g_v);
    cudaGetSymbolAddress((void**)&logits, g_logits);
    cudaGetSymbolAddress((void**)&rsum,   g_rsum);

    const float scale = 0.044194173824159216f;  // 1/sqrt(512)

    cudaFuncSetAttribute(mma_gemm<0>, cudaFuncAttributeMaxDynamicSharedMemorySize, SMEM_BYTES);
    cudaFuncSetAttribute(mma_gemm<1>, cudaFuncAttributeMaxDynamicSharedMemorySize, SMEM_BYTES);
    cudaFuncSetAttribute(mma_gemm<2>, cudaFuncAttributeMaxDynamicSharedMemorySize, SMEM_BYTES);

    // Fused QKV projections: one launch, z selects W/b/C
    {
        dim3 grid(KD / 128, (BATCH * SEQ) / 128, 3);
        mma_gemm<0><<<grid, 256, SMEM_BYTES>>>(
            x, Wq, bq, nullptr, q,
            FEAT, KD, KD, FEAT, 0, 0, 0, 1.0f,
            Wk, Wv, bk, bv, k, v);
    }

    // logits = scale * Q @ K^T : triangular grid, 136 tiles/batch
    {
        dim3 grid(136, 1, BATCH);
        mma_gemm<1><<<grid, 256, SMEM_BYTES>>>(
            q, k, nullptr, nullptr, logits,
            KD, KD, SEQ, KD,
            (long long)SEQ * KD, (long long)SEQ * KD, (long long)SEQ * SEQ, scale,
            nullptr, nullptr, nullptr, nullptr, nullptr, nullptr);
    }

    // softmax: warp per row, 8 warps/block
    softmax_kernel<<<(BATCH * SEQ) / 8, 256>>>(logits, rsum);

    // read = (P @ V) * rowscale, into out[..., FEAT:], K clamped to band,
    // plus folded copy of x into out[..., 0:FEAT]
    {
        dim3 grid(VD / 128, SEQ / 128, BATCH);
        mma_gemm<2><<<grid, 256, SMEM_BYTES>>>(
            logits, v, nullptr, rsum, out + FEAT,
            SEQ, VD, OUTD, SEQ,
            (long long)SEQ * SEQ, (long long)SEQ * VD, (long long)SEQ * OUTD, 1.0f,
            x, nullptr, nullptr, nullptr, nullptr, nullptr);
    }
}

// round 8
// speedup vs baseline: 1.0391x; 1.0391x over previous
#include <cuda_runtime.h>
#include <math.h>
#include <stdint.h>

// Problem constants
#define BATCH 8
#define SEQ   2048
#define FEAT  1024
#define KD    512
#define VD    512
#define OUTD  1536   // FEAT + VD

// Scratch (device globals; no allocations allowed)
__device__ float g_q[BATCH * SEQ * KD];
__device__ float g_k[BATCH * SEQ * KD];
__device__ float g_v[BATCH * SEQ * VD];
__device__ float g_logits[BATCH * SEQ * SEQ];   // probs, unnormalized
__device__ float g_rsum[BATCH * SEQ];           // 1/rowsum for PV epilogue

// 3-stage smem: per stage, A = 128x32 words (16KB) + B = 4096 words (16KB)
#define STAGE_WORDS 8192
#define SMEM_BYTES  (3 * STAGE_WORDS * 4)       // 96 KB

__device__ __forceinline__ void cp16(uint32_t* dst, const void* src) {
    uint32_t a = (uint32_t)__cvta_generic_to_shared(dst);
    asm volatile("cp.async.cg.shared.global [%0], [%1], 16;\n" :: "r"(a), "l"(src));
}
__device__ __forceinline__ void cp_commit() {
    asm volatile("cp.async.commit_group;\n" ::: "memory");
}
__device__ __forceinline__ void cp_wait1() {
    asm volatile("cp.async.wait_group 1;\n" ::: "memory");
}

// ---------------------------------------------------------------------------
// Tensor-core GEMM (mma m16n8k8 tf32, raw fp32 bits = RZ truncation)
// CTA tile 128x128, BK=32, 3-stage cp.async pipeline, XOR-swizzled smem,
// one __syncthreads per k-iteration, 2 CTAs/SM.
// MODE 0: fused QKV projection. NN. blockIdx.z in {0,1,2} selects (B,bias,C).
// MODE 1: QK^T. NT. 1D triangular grid (136 lower-tri tiles).
// MODE 2: PV.  NN, causal K clamp, rowscale epilogue, + x-copy into out.
// ---------------------------------------------------------------------------
template<int MODE>
__global__ __launch_bounds__(256, 2) void mma_gemm(
    const float* __restrict__ A,
    const float* __restrict__ B,
    const float* __restrict__ bias,
    const float* __restrict__ rowscale,
    float* __restrict__ C,
    int lda, int ldb, int ldc, int K,
    long long sA, long long sB, long long sC,
    float alpha,
    const float* __restrict__ B1, const float* __restrict__ B2,
    const float* __restrict__ bias1, const float* __restrict__ bias2,
    float* __restrict__ C1, float* __restrict__ C2)
{
    constexpr bool BT       = (MODE == 1);
    constexpr bool CAUSAL_K = (MODE == 2);

    int m0, n0;
    if (MODE == 1) {
        const int t = blockIdx.x;
        int i = (int)((sqrtf(8.0f * (float)t + 1.0f) - 1.0f) * 0.5f);
        if ((i + 1) * (i + 2) / 2 <= t) i++;
        if (i * (i + 1) / 2 > t) i--;
        const int j = t - i * (i + 1) / 2;
        m0 = i * 128;
        n0 = j * 128;
    } else {
        m0 = blockIdx.y * 128;
        n0 = blockIdx.x * 128;
    }

    const int z = blockIdx.z;
    if (MODE == 0) {
        if (z == 1) { B = B1; bias = bias1; C = C1; }
        else if (z == 2) { B = B2; bias = bias2; C = C2; }
    } else {
        A += (long long)z * sA;
        B += (long long)z * sB;
        C += (long long)z * sC;
        if (MODE == 2) rowscale += (long long)z * SEQ;
    }

    const int K_end = CAUSAL_K ? (K < m0 + 128 ? K : m0 + 128) : K;
    const int n_iter = K_end >> 5;

    extern __shared__ uint32_t smem[];

    const int tid  = threadIdx.x;
    const int lane = tid & 31;
    const int w    = tid >> 5;
    const int wm   = w & 1;       // 0..1
    const int wn   = w >> 1;      // 0..3
    const int l4   = lane >> 2;   // 0..7
    const int lm   = lane & 3;    // 0..3

    // XOR-swizzled staging:
    //   A / B-NT: word (r,c) -> r*32 + (c ^ ((r&7)<<2))
    //   B-NN:     word (k,n) -> k*128 + (n ^ ((k&3)<<3))
    auto load_tile = [&](int k0, int s) {
        uint32_t* Sa = smem + s * STAGE_WORDS;
        uint32_t* Sb = Sa + 4096;
        #pragma unroll
        for (int i = 0; i < 4; i++) {
            const int idx = tid + i * 256;
            const int r   = idx >> 3;
            const int c4  = (idx & 7) << 2;
            cp16(&Sa[r * 32 + (c4 ^ ((r & 7) << 2))],
                 &A[(long long)(m0 + r) * lda + k0 + c4]);
        }
        if (BT) {
            #pragma unroll
            for (int i = 0; i < 4; i++) {
                const int idx = tid + i * 256;
                const int r   = idx >> 3;
                const int c4  = (idx & 7) << 2;
                cp16(&Sb[r * 32 + (c4 ^ ((r & 7) << 2))],
                     &B[(long long)(n0 + r) * ldb + k0 + c4]);
            }
        } else {
            #pragma unroll
            for (int i = 0; i < 4; i++) {
                const int idx = tid + i * 256;
                const int kk  = idx >> 5;
                const int n4  = (idx & 31) << 2;
                cp16(&Sb[kk * 128 + (n4 ^ ((kk & 3) << 3))],
                     &B[(long long)(k0 + kk) * ldb + n0 + n4]);
            }
        }
    };

    float acc[4][4][4];
    #pragma unroll
    for (int i = 0; i < 4; i++)
        #pragma unroll
        for (int j = 0; j < 4; j++)
            #pragma unroll
            for (int r = 0; r < 4; r++) acc[i][j][r] = 0.0f;

    // prologue: stages 0 and 1 in flight
    load_tile(0, 0);
    cp_commit();
    if (1 < n_iter) load_tile(32, 1);
    cp_commit();

    int s = 0;        // compute stage
    int ls = 2;       // next load stage
    for (int it = 0; it < n_iter; it++) {
        cp_wait1();           // group `it` complete (committed 2 iters ago)
        __syncthreads();      // WAR: everyone done with buffer (it-1)%3

        if (it + 2 < n_iter) load_tile((it + 2) << 5, ls);
        cp_commit();          // keep group numbering iteration-aligned

        const uint32_t* Sa = smem + s * STAGE_WORDS;
        const uint32_t* Sb = Sa + 4096;

        #pragma unroll
        for (int ks = 0; ks < 4; ks++) {
            const int kk = ks * 8;
            uint32_t a[4][4];
            uint32_t b[4][2];
            #pragma unroll
            for (int tm = 0; tm < 4; tm++) {
                const int r0 = wm * 64 + tm * 16 + l4;
                const int c0 = (kk + lm) ^ (l4 << 2);
                const int c1 = (kk + lm + 4) ^ (l4 << 2);
                a[tm][0] = Sa[r0 * 32 + c0];
                a[tm][1] = Sa[(r0 + 8) * 32 + c0];
                a[tm][2] = Sa[r0 * 32 + c1];
                a[tm][3] = Sa[(r0 + 8) * 32 + c1];
            }
            #pragma unroll
            for (int tn = 0; tn < 4; tn++) {
                if (BT) {
                    const int rb = wn * 32 + tn * 8 + l4;
                    b[tn][0] = Sb[rb * 32 + ((kk + lm) ^ (l4 << 2))];
                    b[tn][1] = Sb[rb * 32 + ((kk + lm + 4) ^ (l4 << 2))];
                } else {
                    const int col = (wn * 32 + tn * 8 + l4) ^ (lm << 3);
                    b[tn][0] = Sb[(kk + lm) * 128 + col];
                    b[tn][1] = Sb[(kk + lm + 4) * 128 + col];
                }
            }
            #pragma unroll
            for (int tm = 0; tm < 4; tm++)
                #pragma unroll
                for (int tn = 0; tn < 4; tn++) {
                    asm volatile(
                        "mma.sync.aligned.m16n8k8.row.col.f32.tf32.tf32.f32 "
                        "{%0,%1,%2,%3}, {%4,%5,%6,%7}, {%8,%9}, {%0,%1,%2,%3};\n"
                        : "+f"(acc[tm][tn][0]), "+f"(acc[tm][tn][1]),
                          "+f"(acc[tm][tn][2]), "+f"(acc[tm][tn][3])
                        : "r"(a[tm][0]), "r"(a[tm][1]), "r"(a[tm][2]), "r"(a[tm][3]),
                          "r"(b[tn][0]), "r"(b[tn][1]));
                }
        }
        s  = (s  == 2) ? 0 : s + 1;
        ls = (ls == 2) ? 0 : ls + 1;
    }

    // ---- epilogue ----
    #pragma unroll
    for (int tm = 0; tm < 4; tm++) {
        const int row = m0 + wm * 64 + tm * 16 + l4;
        float f0 = alpha, f1 = alpha;
        if (MODE == 2) { f0 = alpha * rowscale[row]; f1 = alpha * rowscale[row + 8]; }
        #pragma unroll
        for (int tn = 0; tn < 4; tn++) {
            const int col = n0 + wn * 32 + tn * 8 + (lm << 1);
            float bx = 0.0f, by = 0.0f;
            if (MODE == 0) { bx = bias[col]; by = bias[col + 1]; }
            float2 v0, v1;
            v0.x = acc[tm][tn][0] * f0 + bx;
            v0.y = acc[tm][tn][1] * f0 + by;
            v1.x = acc[tm][tn][2] * f1 + bx;
            v1.y = acc[tm][tn][3] * f1 + by;
            *(float2*)&C[(long long)row * ldc + col]       = v0;
            *(float2*)&C[(long long)(row + 8) * ldc + col] = v1;
        }
    }

    // ---- MODE 2: fold x-copy into PV tail (this CTA's 128x256 x block) ----
    if (MODE == 2) {
        const float4* x4 = (const float4*)B1;   // x viewed as [BATCH*SEQ, 256] float4
        float4* o4 = (float4*)(C - FEAT);       // out rows, OUTD floats = 384 float4
        const int xc0 = (int)blockIdx.x * 64;   // this n-tile's float4 col range in x
        #pragma unroll 4
        for (int i = tid; i < 128 * 64; i += 256) {
            const int r  = i >> 6;
            const int c4 = i & 63;
            const long long grow = (long long)z * SEQ + m0 + r;
            o4[(long long)(m0 + r) * 384 + xc0 + c4] = x4[grow * 256 + xc0 + c4];
        }
    }
}

// ---------------------------------------------------------------------------
// Warp-per-row softmax (unnormalized): p[i]=exp(p[i]-max); rsum=1/sum.
// Zeros the band tail [q+1, ceil128(q+1)) that PV's clamped K-loop touches.
// ---------------------------------------------------------------------------
__global__ __launch_bounds__(256) void softmax_kernel(float* __restrict__ logits,
                                                      float* __restrict__ rsum)
{
    const int wid  = threadIdx.x >> 5;
    const int lane = threadIdx.x & 31;
    const long long row = (long long)blockIdx.x * 8 + wid;
    const int q = (int)(row % SEQ);
    float* p = logits + row * SEQ;
    const int len  = q + 1;
    const int len4 = len >> 2;
    const int band = ((q >> 7) + 1) << 7;
    float4* p4 = (float4*)p;

    float mx = -INFINITY;
    for (int i = lane; i < len4; i += 32) {
        float4 v = p4[i];
        mx = fmaxf(mx, fmaxf(fmaxf(v.x, v.y), fmaxf(v.z, v.w)));
    }
    for (int i = (len4 << 2) + lane; i < len; i += 32) mx = fmaxf(mx, p[i]);
    #pragma unroll
    for (int o = 16; o > 0; o >>= 1)
        mx = fmaxf(mx, __shfl_xor_sync(0xffffffffu, mx, o));

    float sum = 0.0f;
    for (int i = lane; i < len4; i += 32) {
        float4 v = p4[i];
        v.x = __expf(v.x - mx);
        v.y = __expf(v.y - mx);
        v.z = __expf(v.z - mx);
        v.w = __expf(v.w - mx);
        p4[i] = v;
        sum += (v.x + v.y) + (v.z + v.w);
    }
    for (int i = (len4 << 2) + lane; i < len; i += 32) {
        float e = __expf(p[i] - mx);
        p[i] = e;
        sum += e;
    }
    #pragma unroll
    for (int o = 16; o > 0; o >>= 1)
        sum += __shfl_xor_sync(0xffffffffu, sum, o);

    if (lane == 0) rsum[row] = 1.0f / sum;

    for (int i = len + lane; i < band; i += 32) p[i] = 0.0f;
}

// ---------------------------------------------------------------------------
extern "C" void kernel_launch(void* const* d_in, const int* in_sizes, int n_in,
                              void* d_out, int out_size)
{
    const float* x  = (const float*)d_in[0];
    const float* Wq = (const float*)d_in[1];
    const float* bq = (const float*)d_in[2];
    const float* Wk = (const float*)d_in[3];
    const float* bk = (const float*)d_in[4];
    const float* Wv = (const float*)d_in[5];
    const float* bv = (const float*)d_in[6];
    float* out = (float*)d_out;

    float *q, *k, *v, *logits, *rsum;
    cudaGetSymbolAddress((void**)&q,      g_q);
    cudaGetSymbolAddress((void**)&k,      g_k);
    cudaGetSymbolAddress((void**)&v,      g_v);
    cudaGetSymbolAddress((void**)&logits, g_logits);
    cudaGetSymbolAddress((void**)&rsum,   g_rsum);

    const float scale = 0.044194173824159216f;  // 1/sqrt(512)

    cudaFuncSetAttribute(mma_gemm<0>, cudaFuncAttributeMaxDynamicSharedMemorySize, SMEM_BYTES);
    cudaFuncSetAttribute(mma_gemm<1>, cudaFuncAttributeMaxDynamicSharedMemorySize, SMEM_BYTES);
    cudaFuncSetAttribute(mma_gemm<2>, cudaFuncAttributeMaxDynamicSharedMemorySize, SMEM_BYTES);

    // Fused QKV projections: one launch, z selects W/b/C
    {
        dim3 grid(KD / 128, (BATCH * SEQ) / 128, 3);
        mma_gemm<0><<<grid, 256, SMEM_BYTES>>>(
            x, Wq, bq, nullptr, q,
            FEAT, KD, KD, FEAT, 0, 0, 0, 1.0f,
            Wk, Wv, bk, bv, k, v);
    }

    // logits = scale * Q @ K^T : triangular grid, 136 tiles/batch
    {
        dim3 grid(136, 1, BATCH);
        mma_gemm<1><<<grid, 256, SMEM_BYTES>>>(
            q, k, nullptr, nullptr, logits,
            KD, KD, SEQ, KD,
            (long long)SEQ * KD, (long long)SEQ * KD, (long long)SEQ * SEQ, scale,
            nullptr, nullptr, nullptr, nullptr, nullptr, nullptr);
    }

    // softmax: warp per row, 8 warps/block
    softmax_kernel<<<(BATCH * SEQ) / 8, 256>>>(logits, rsum);

    // read = (P @ V) * rowscale, into out[..., FEAT:], K clamped to band,
    // plus folded copy of x into out[..., 0:FEAT]
    {
        dim3 grid(VD / 128, SEQ / 128, BATCH);
        mma_gemm<2><<<grid, 256, SMEM_BYTES>>>(
            logits, v, nullptr, rsum, out + FEAT,
            SEQ, VD, OUTD, SEQ,
            (long long)SEQ * SEQ, (long long)SEQ * VD, (long long)SEQ * OUTD, 1.0f,
            x, nullptr, nullptr, nullptr, nullptr, nullptr);
    }
}

// round 9
// speedup vs baseline: 1.5702x; 1.5112x over previous
#include <cuda_runtime.h>
#include <cuda_fp16.h>
#include <math.h>
#include <stdint.h>

// Problem constants
#define BATCH 8
#define SEQ   2048
#define FEAT  1024
#define KD    512
#define VD    512
#define OUTD  1536   // FEAT + VD
#define MROWS (BATCH * SEQ)   // 16384

// Scratch (device globals; no allocations allowed)
__device__ __half g_xh[MROWS * FEAT];           // x in fp16
__device__ __half g_wt[3 * KD * FEAT];          // Wq/Wk/Wv transposed [n, k] fp16
__device__ __half g_qh[MROWS * KD];
__device__ __half g_kh[MROWS * KD];
__device__ __half g_vt[VD * MROWS];             // v transposed: [vd, b*S]
__device__ float  g_logits[BATCH * SEQ * SEQ];  // fp32 logits
__device__ __half g_ph[BATCH * SEQ * SEQ];      // unnormalized probs fp16
__device__ float  g_rsum[BATCH * SEQ];          // 1/rowsum

// 3-stage smem: per stage, A = 128x32 words (16KB) + B = 128x32 words (16KB)
// (words are uint32 = half2; 32 words = 64 halfs = 128B per row)
#define STAGE_WORDS 8192
#define SMEM_BYTES  (3 * STAGE_WORDS * 4)       // 96 KB

__device__ __forceinline__ void cp16(uint32_t* dst, const void* src) {
    uint32_t a = (uint32_t)__cvta_generic_to_shared(dst);
    asm volatile("cp.async.cg.shared.global [%0], [%1], 16;\n" :: "r"(a), "l"(src));
}
__device__ __forceinline__ void cp_commit() {
    asm volatile("cp.async.commit_group;\n" ::: "memory");
}
__device__ __forceinline__ void cp_wait1() {
    asm volatile("cp.async.wait_group 1;\n" ::: "memory");
}

// ---------------------------------------------------------------------------
// fp16 tensor-core GEMM (mma m16n8k16, fp32 accum)
// CTA tile 128x128, BK=64 halfs, 3-stage cp.async, XOR-swizzled smem,
// one __syncthreads per iter, 2 CTAs/SM. A row-major [M,K], B n-major [N,K].
// MODE 0: fused QKV. z in {0,1,2}: C=qh / C1=kh / C2=vt (transposed store).
// MODE 1: QK^T -> fp32 logits * alpha. Triangular 1D grid.
// MODE 2: PV (A=probs fp16, B=vt). Causal K clamp, rowscale epilogue, fp32 out.
// ---------------------------------------------------------------------------
template<int MODE>
__global__ __launch_bounds__(256, 2) void mma_gemm(
    const __half* __restrict__ A,
    const __half* __restrict__ B,
    const float* __restrict__ bias0,
    const float* __restrict__ bias1,
    const float* __restrict__ bias2,
    const float* __restrict__ rowscale,
    void* __restrict__ Cv,
    void* __restrict__ C1v,
    void* __restrict__ C2v,
    int lda, int ldb, int ldc, int K,
    long long sA, long long sB, long long sC,
    float alpha)
{
    constexpr bool CAUSAL_K = (MODE == 2);

    int m0, n0;
    if (MODE == 1) {
        const int t = blockIdx.x;
        int i = (int)((sqrtf(8.0f * (float)t + 1.0f) - 1.0f) * 0.5f);
        if ((i + 1) * (i + 2) / 2 <= t) i++;
        if (i * (i + 1) / 2 > t) i--;
        const int j = t - i * (i + 1) / 2;
        m0 = i * 128;
        n0 = j * 128;
    } else {
        m0 = blockIdx.y * 128;
        n0 = blockIdx.x * 128;
    }

    const int z = blockIdx.z;
    const float* bias = bias0;
    if (MODE == 0) {
        B += (long long)z * KD * FEAT;          // Wt slice
        if (z == 1) bias = bias1;
        if (z == 2) bias = bias2;
    } else {
        A += (long long)z * sA;
        B += (long long)z * sB;
        if (MODE == 2) rowscale += (long long)z * SEQ;
    }

    const int K_end = CAUSAL_K ? (K < m0 + 128 ? K : m0 + 128) : K;
    const int n_iter = K_end >> 6;

    extern __shared__ uint32_t smem[];

    const int tid  = threadIdx.x;
    const int lane = tid & 31;
    const int w    = tid >> 5;
    const int wm   = w & 1;
    const int wn   = w >> 1;
    const int l4   = lane >> 2;   // 0..7
    const int lm   = lane & 3;    // 0..3

    // XOR-swizzled staging: word (r,c) -> r*32 + (c ^ ((r&7)<<2)), c in [0,32)
    auto load_tile = [&](int k0, int s) {
        uint32_t* Sa = smem + s * STAGE_WORDS;
        uint32_t* Sb = Sa + 4096;
        #pragma unroll
        for (int i = 0; i < 4; i++) {
            const int idx = tid + i * 256;
            const int r   = idx >> 3;
            const int c4  = (idx & 7) << 2;            // word offset
            cp16(&Sa[r * 32 + (c4 ^ ((r & 7) << 2))],
                 &A[(long long)(m0 + r) * lda + k0 + (c4 << 1)]);
        }
        #pragma unroll
        for (int i = 0; i < 4; i++) {
            const int idx = tid + i * 256;
            const int r   = idx >> 3;
            const int c4  = (idx & 7) << 2;
            cp16(&Sb[r * 32 + (c4 ^ ((r & 7) << 2))],
                 &B[(long long)(n0 + r) * ldb + k0 + (c4 << 1)]);
        }
    };

    float acc[4][4][4];
    #pragma unroll
    for (int i = 0; i < 4; i++)
        #pragma unroll
        for (int j = 0; j < 4; j++)
            #pragma unroll
            for (int r = 0; r < 4; r++) acc[i][j][r] = 0.0f;

    load_tile(0, 0);
    cp_commit();
    if (1 < n_iter) load_tile(64, 1);
    cp_commit();

    int s = 0, ls = 2;
    for (int it = 0; it < n_iter; it++) {
        cp_wait1();
        __syncthreads();

        if (it + 2 < n_iter) load_tile((it + 2) << 6, ls);
        cp_commit();

        const uint32_t* Sa = smem + s * STAGE_WORDS;
        const uint32_t* Sb = Sa + 4096;

        #pragma unroll
        for (int ks = 0; ks < 4; ks++) {      // 4 x k16 steps = 64 halfs
            const int kk = ks * 8;            // word offset of this k16 step
            uint32_t a[4][4];
            uint32_t b[4][2];
            #pragma unroll
            for (int tm = 0; tm < 4; tm++) {
                const int r0 = wm * 64 + tm * 16 + l4;
                const int c0 = (kk + lm) ^ (l4 << 2);
                const int c1 = (kk + lm + 4) ^ (l4 << 2);
                a[tm][0] = Sa[r0 * 32 + c0];
                a[tm][1] = Sa[(r0 + 8) * 32 + c0];
                a[tm][2] = Sa[r0 * 32 + c1];
                a[tm][3] = Sa[(r0 + 8) * 32 + c1];
            }
            #pragma unroll
            for (int tn = 0; tn < 4; tn++) {
                const int rb = wn * 32 + tn * 8 + l4;
                b[tn][0] = Sb[rb * 32 + ((kk + lm) ^ (l4 << 2))];
                b[tn][1] = Sb[rb * 32 + ((kk + lm + 4) ^ (l4 << 2))];
            }
            #pragma unroll
            for (int tm = 0; tm < 4; tm++)
                #pragma unroll
                for (int tn = 0; tn < 4; tn++) {
                    asm volatile(
                        "mma.sync.aligned.m16n8k16.row.col.f32.f16.f16.f32 "
                        "{%0,%1,%2,%3}, {%4,%5,%6,%7}, {%8,%9}, {%0,%1,%2,%3};\n"
                        : "+f"(acc[tm][tn][0]), "+f"(acc[tm][tn][1]),
                          "+f"(acc[tm][tn][2]), "+f"(acc[tm][tn][3])
                        : "r"(a[tm][0]), "r"(a[tm][1]), "r"(a[tm][2]), "r"(a[tm][3]),
                          "r"(b[tn][0]), "r"(b[tn][1]));
                }
        }
        s  = (s  == 2) ? 0 : s + 1;
        ls = (ls == 2) ? 0 : ls + 1;
    }

    // ---- epilogue ----
    #pragma unroll
    for (int tm = 0; tm < 4; tm++) {
        const int row = m0 + wm * 64 + tm * 16 + l4;
        float f0 = alpha, f1 = alpha;
        if (MODE == 2) { f0 = alpha * rowscale[row]; f1 = alpha * rowscale[row + 8]; }
        #pragma unroll
        for (int tn = 0; tn < 4; tn++) {
            const int col = n0 + wn * 32 + tn * 8 + (lm << 1);
            if (MODE == 0) {
                const float bx = bias[col], by = bias[col + 1];
                const float v0x = acc[tm][tn][0] + bx, v0y = acc[tm][tn][1] + by;
                const float v1x = acc[tm][tn][2] + bx, v1y = acc[tm][tn][3] + by;
                if (z < 2) {
                    __half* O = (__half*)(z ? C1v : Cv);
                    *(__half2*)&O[(long long)row * KD + col] = __floats2half2_rn(v0x, v0y);
                    *(__half2*)&O[(long long)(row + 8) * KD + col] = __floats2half2_rn(v1x, v1y);
                } else {
                    __half* T = (__half*)C2v;    // [VD][MROWS]
                    T[(long long)col * MROWS + row]           = __float2half_rn(v0x);
                    T[(long long)(col + 1) * MROWS + row]     = __float2half_rn(v0y);
                    T[(long long)col * MROWS + row + 8]       = __float2half_rn(v1x);
                    T[(long long)(col + 1) * MROWS + row + 8] = __float2half_rn(v1y);
                }
            } else {
                float* O = (float*)Cv + (long long)z * sC;
                float2 v0, v1;
                v0.x = acc[tm][tn][0] * f0;
                v0.y = acc[tm][tn][1] * f0;
                v1.x = acc[tm][tn][2] * f1;
                v1.y = acc[tm][tn][3] * f1;
                *(float2*)&O[(long long)row * ldc + col]       = v0;
                *(float2*)&O[(long long)(row + 8) * ldc + col] = v1;
            }
        }
    }
}

// ---------------------------------------------------------------------------
// Prep: x -> fp16
// ---------------------------------------------------------------------------
__global__ __launch_bounds__(256) void cvt_x_kernel(const float4* __restrict__ x,
                                                    uint2* __restrict__ xh)
{
    const long long i = (long long)blockIdx.x * 256 + threadIdx.x;
    if (i >= (long long)MROWS * FEAT / 4) return;
    float4 v = x[i];
    __half2 h0 = __floats2half2_rn(v.x, v.y);
    __half2 h1 = __floats2half2_rn(v.z, v.w);
    uint2 u;
    u.x = *(uint32_t*)&h0;
    u.y = *(uint32_t*)&h1;
    xh[i] = u;
}

// Prep: W[k][n] fp32 -> Wt[z][n][k] fp16
__global__ __launch_bounds__(256) void cvt_w_kernel(const float* __restrict__ Wq,
                                                    const float* __restrict__ Wk,
                                                    const float* __restrict__ Wv,
                                                    __half* __restrict__ Wt)
{
    const int i = blockIdx.x * 256 + threadIdx.x;
    if (i >= 3 * FEAT * KD) return;
    const int zz = i / (FEAT * KD);
    const int r  = (i / KD) % FEAT;      // k
    const int n  = i % KD;
    const float* W = (zz == 0) ? Wq : (zz == 1) ? Wk : Wv;
    Wt[(long long)zz * KD * FEAT + (long long)n * FEAT + r] = __float2half_rn(W[(long long)r * KD + n]);
}

// ---------------------------------------------------------------------------
// Warp-per-row softmax: reads fp32 logits, writes unnormalized fp16 probs
// (zeros fused in up to the 128-aligned band end); rsum = 1/sum.
// ---------------------------------------------------------------------------
__global__ __launch_bounds__(256) void softmax_kernel(const float* __restrict__ logits,
                                                      __half* __restrict__ probs,
                                                      float* __restrict__ rsum)
{
    const int wid  = threadIdx.x >> 5;
    const int lane = threadIdx.x & 31;
    const long long row = (long long)blockIdx.x * 8 + wid;
    const int q = (int)(row % SEQ);
    const float* p = logits + row * SEQ;
    __half2* o2 = (__half2*)(probs + row * SEQ);
    const int len  = q + 1;
    const int len4 = len >> 2;
    const int band2 = (((q >> 7) + 1) << 7) >> 1;   // half2 count

    float mx = -INFINITY;
    const float4* p4 = (const float4*)p;
    for (int i = lane; i < len4; i += 32) {
        float4 v = p4[i];
        mx = fmaxf(mx, fmaxf(fmaxf(v.x, v.y), fmaxf(v.z, v.w)));
    }
    for (int i = (len4 << 2) + lane; i < len; i += 32) mx = fmaxf(mx, p[i]);
    #pragma unroll
    for (int o = 16; o > 0; o >>= 1)
        mx = fmaxf(mx, __shfl_xor_sync(0xffffffffu, mx, o));

    float sum = 0.0f;
    const float2* p2 = (const float2*)p;
    for (int i = lane; i < band2; i += 32) {
        float2 v = p2[i];
        const int e0 = 2 * i, e1 = 2 * i + 1;
        float w0 = (e0 < len) ? __expf(v.x - mx) : 0.0f;
        float w1 = (e1 < len) ? __expf(v.y - mx) : 0.0f;
        sum += w0 + w1;
        o2[i] = __floats2half2_rn(w0, w1);
    }
    #pragma unroll
    for (int o = 16; o > 0; o >>= 1)
        sum += __shfl_xor_sync(0xffffffffu, sum, o);

    if (lane == 0) rsum[row] = 1.0f / sum;
}

// ---------------------------------------------------------------------------
__global__ __launch_bounds__(256) void copy_x_kernel(const float4* __restrict__ x,
                                                     float4* __restrict__ out)
{
    const long long i = (long long)blockIdx.x * blockDim.x + threadIdx.x;
    const long long total = (long long)MROWS * (FEAT / 4);
    if (i >= total) return;
    const long long row = i / (FEAT / 4);
    const int col = (int)(i % (FEAT / 4));
    out[row * (OUTD / 4) + col] = x[i];
}

// ---------------------------------------------------------------------------
extern "C" void kernel_launch(void* const* d_in, const int* in_sizes, int n_in,
                              void* d_out, int out_size)
{
    const float* x  = (const float*)d_in[0];
    const float* Wq = (const float*)d_in[1];
    const float* bq = (const float*)d_in[2];
    const float* Wk = (const float*)d_in[3];
    const float* bk = (const float*)d_in[4];
    const float* Wv = (const float*)d_in[5];
    const float* bv = (const float*)d_in[6];
    float* out = (float*)d_out;

    __half *xh, *wt, *qh, *kh, *vt, *ph;
    float *logits, *rsum;
    cudaGetSymbolAddress((void**)&xh,     g_xh);
    cudaGetSymbolAddress((void**)&wt,     g_wt);
    cudaGetSymbolAddress((void**)&qh,     g_qh);
    cudaGetSymbolAddress((void**)&kh,     g_kh);
    cudaGetSymbolAddress((void**)&vt,     g_vt);
    cudaGetSymbolAddress((void**)&ph,     g_ph);
    cudaGetSymbolAddress((void**)&logits, g_logits);
    cudaGetSymbolAddress((void**)&rsum,   g_rsum);

    const float scale = 0.044194173824159216f;  // 1/sqrt(512)

    cudaFuncSetAttribute(mma_gemm<0>, cudaFuncAttributeMaxDynamicSharedMemorySize, SMEM_BYTES);
    cudaFuncSetAttribute(mma_gemm<1>, cudaFuncAttributeMaxDynamicSharedMemorySize, SMEM_BYTES);
    cudaFuncSetAttribute(mma_gemm<2>, cudaFuncAttributeMaxDynamicSharedMemorySize, SMEM_BYTES);

    // prep: fp16 conversions
    cvt_x_kernel<<<(MROWS * FEAT / 4 + 255) / 256, 256>>>((const float4*)x, (uint2*)xh);
    cvt_w_kernel<<<(3 * FEAT * KD + 255) / 256, 256>>>(Wq, Wk, Wv, wt);

    // Fused QKV projections (z: q / k / v-transposed)
    {
        dim3 grid(KD / 128, MROWS / 128, 3);
        mma_gemm<0><<<grid, 256, SMEM_BYTES>>>(
            xh, wt, bq, bk, bv, nullptr, qh, kh, vt,
            FEAT, FEAT, 0, FEAT, 0, 0, 0, 1.0f);
    }

    // logits = scale * Q @ K^T : triangular grid
    {
        dim3 grid(136, 1, BATCH);
        mma_gemm<1><<<grid, 256, SMEM_BYTES>>>(
            qh, kh, nullptr, nullptr, nullptr, nullptr, logits, nullptr, nullptr,
            KD, KD, SEQ, KD,
            (long long)SEQ * KD, (long long)SEQ * KD, (long long)SEQ * SEQ, scale);
    }

    // softmax: fp32 logits -> fp16 unnormalized probs (+band zero), 1/sum
    softmax_kernel<<<MROWS / 8, 256>>>(logits, ph, rsum);

    // read = (P @ V) * rowscale -> out[..., FEAT:]
    {
        dim3 grid(VD / 128, SEQ / 128, BATCH);
        mma_gemm<2><<<grid, 256, SMEM_BYTES>>>(
            ph, vt, nullptr, nullptr, nullptr, rsum, out + FEAT, nullptr, nullptr,
            SEQ, MROWS, OUTD, SEQ,
            (long long)SEQ * SEQ, SEQ, (long long)SEQ * OUTD, 1.0f);
    }

    // out[..., 0:FEAT] = x
    copy_x_kernel<<<(int)(((long long)MROWS * (FEAT / 4) + 255) / 256), 256>>>(
        (const float4*)x, (float4*)out);
}

// round 10
// speedup vs baseline: 1.8246x; 1.1620x over previous
#include <cuda_runtime.h>
#include <cuda_fp16.h>
#include <math.h>
#include <stdint.h>

// Problem constants
#define BATCH 8
#define SEQ   2048
#define FEAT  1024
#define KD    512
#define VD    512
#define OUTD  1536   // FEAT + VD
#define MROWS (BATCH * SEQ)   // 16384

// Scratch (device globals; no allocations allowed)
__device__ __half g_xh[MROWS * FEAT];           // x in fp16
__device__ __half g_wt[3 * KD * FEAT];          // Wq/Wk/Wv transposed [n, k] fp16
__device__ __half g_qh[MROWS * KD];
__device__ __half g_kh[MROWS * KD];
__device__ __half g_vt[VD * MROWS];             // v transposed: [vd, b*S]
__device__ float  g_logits[BATCH * SEQ * SEQ];  // fp32 logits
__device__ __half g_ph[BATCH * SEQ * SEQ];      // unnormalized probs fp16
__device__ float  g_rsum[BATCH * SEQ];          // 1/rowsum

// 3-stage smem: per stage, A = 128 rows x 32 words (16KB) + B same (16KB)
#define STAGE_WORDS 8192
#define STAGE_BYTES (STAGE_WORDS * 4)
#define SMEM_BYTES  (3 * STAGE_BYTES)           // 96 KB

__device__ __forceinline__ void cp16(uint32_t* dst, const void* src) {
    uint32_t a = (uint32_t)__cvta_generic_to_shared(dst);
    asm volatile("cp.async.cg.shared.global [%0], [%1], 16;\n" :: "r"(a), "l"(src));
}
__device__ __forceinline__ void cp_commit() {
    asm volatile("cp.async.commit_group;\n" ::: "memory");
}
__device__ __forceinline__ void cp_wait1() {
    asm volatile("cp.async.wait_group 1;\n" ::: "memory");
}
__device__ __forceinline__ void ldsm4(uint32_t* r, uint32_t addr) {
    asm volatile("ldmatrix.sync.aligned.m8n8.x4.shared.b16 {%0,%1,%2,%3}, [%4];"
        : "=r"(r[0]), "=r"(r[1]), "=r"(r[2]), "=r"(r[3]) : "r"(addr));
}
__device__ __forceinline__ void ldsm2(uint32_t* r, uint32_t addr) {
    asm volatile("ldmatrix.sync.aligned.m8n8.x2.shared.b16 {%0,%1}, [%2];"
        : "=r"(r[0]), "=r"(r[1]) : "r"(addr));
}

// ---------------------------------------------------------------------------
// fp16 tensor-core GEMM (mma m16n8k16, fp32 accum), ldmatrix fragment loads.
// CTA tile 128x128, BK=64 halfs, 3-stage cp.async, XOR-swizzled smem,
// one __syncthreads per iter, 2 CTAs/SM. A row-major [M,K], B n-major [N,K].
// MODE 0: fused QKV. z in {0,1,2}: C=qh / C1=kh / C2=vt (transposed store).
// MODE 1: QK^T -> fp32 logits * alpha. Triangular 1D grid.
// MODE 2: PV (A=probs fp16, B=vt). Causal K clamp, rowscale epilogue, fp32 out.
// ---------------------------------------------------------------------------
template<int MODE>
__global__ __launch_bounds__(256, 2) void mma_gemm(
    const __half* __restrict__ A,
    const __half* __restrict__ B,
    const float* __restrict__ bias0,
    const float* __restrict__ bias1,
    const float* __restrict__ bias2,
    const float* __restrict__ rowscale,
    void* __restrict__ Cv,
    void* __restrict__ C1v,
    void* __restrict__ C2v,
    int lda, int ldb, int ldc, int K,
    long long sA, long long sB, long long sC,
    float alpha)
{
    constexpr bool CAUSAL_K = (MODE == 2);

    int m0, n0;
    if (MODE == 1) {
        const int t = blockIdx.x;
        int i = (int)((sqrtf(8.0f * (float)t + 1.0f) - 1.0f) * 0.5f);
        if ((i + 1) * (i + 2) / 2 <= t) i++;
        if (i * (i + 1) / 2 > t) i--;
        const int j = t - i * (i + 1) / 2;
        m0 = i * 128;
        n0 = j * 128;
    } else {
        m0 = blockIdx.y * 128;
        n0 = blockIdx.x * 128;
    }

    const int z = blockIdx.z;
    const float* bias = bias0;
    if (MODE == 0) {
        B += (long long)z * KD * FEAT;          // Wt slice
        if (z == 1) bias = bias1;
        if (z == 2) bias = bias2;
    } else {
        A += (long long)z * sA;
        B += (long long)z * sB;
        if (MODE == 2) rowscale += (long long)z * SEQ;
    }

    const int K_end = CAUSAL_K ? (K < m0 + 128 ? K : m0 + 128) : K;
    const int n_iter = K_end >> 6;

    extern __shared__ uint32_t smem[];

    const int tid  = threadIdx.x;
    const int lane = tid & 31;
    const int w    = tid >> 5;
    const int wm   = w & 1;
    const int wn   = w >> 1;

    // XOR-swizzled staging: word (r,c) -> r*32 + (c ^ ((r&7)<<2)), c in [0,32)
    auto load_tile = [&](int k0, int s) {
        uint32_t* Sa = smem + s * STAGE_WORDS;
        uint32_t* Sb = Sa + 4096;
        #pragma unroll
        for (int i = 0; i < 4; i++) {
            const int idx = tid + i * 256;
            const int r   = idx >> 3;
            const int c4  = (idx & 7) << 2;            // word offset
            cp16(&Sa[r * 32 + (c4 ^ ((r & 7) << 2))],
                 &A[(long long)(m0 + r) * lda + k0 + (c4 << 1)]);
        }
        #pragma unroll
        for (int i = 0; i < 4; i++) {
            const int idx = tid + i * 256;
            const int r   = idx >> 3;
            const int c4  = (idx & 7) << 2;
            cp16(&Sb[r * 32 + (c4 ^ ((r & 7) << 2))],
                 &B[(long long)(n0 + r) * ldb + k0 + (c4 << 1)]);
        }
    };

    // ldmatrix per-lane constants
    const uint32_t sbase  = (uint32_t)__cvta_generic_to_shared(smem);
    const uint32_t maskB  = (uint32_t)((lane & 7) << 2);           // word-space swizzle mask
    const uint32_t abase0 = sbase + (uint32_t)((wm * 64 + (lane & 15)) * 128);
    const uint32_t bbase0 = sbase + 16384u + (uint32_t)((wn * 32 + (lane & 7)) * 128);
    const uint32_t cA = (uint32_t)((lane & 16) >> 2);              // 0 or 4 words
    const uint32_t cB = (uint32_t)((lane & 8) >> 1);               // 0 or 4 words

    float acc[4][4][4];
    #pragma unroll
    for (int i = 0; i < 4; i++)
        #pragma unroll
        for (int j = 0; j < 4; j++)
            #pragma unroll
            for (int r = 0; r < 4; r++) acc[i][j][r] = 0.0f;

    load_tile(0, 0);
    cp_commit();
    if (1 < n_iter) load_tile(64, 1);
    cp_commit();

    int s = 0, ls = 2;
    for (int it = 0; it < n_iter; it++) {
        cp_wait1();
        __syncthreads();

        if (it + 2 < n_iter) load_tile((it + 2) << 6, ls);
        cp_commit();

        const uint32_t soff = (uint32_t)(s * STAGE_BYTES);

        #pragma unroll
        for (int ks = 0; ks < 4; ks++) {      // 4 x k16 steps = 64 halfs
            const uint32_t kk = (uint32_t)(ks * 8);   // word offset of this step
            const uint32_t offA = ((kk + cA) ^ maskB) << 2;   // byte offset in row
            const uint32_t offB = ((kk + cB) ^ maskB) << 2;
            uint32_t a[4][4];
            uint32_t b[4][2];
            #pragma unroll
            for (int tm = 0; tm < 4; tm++)
                ldsm4(a[tm], abase0 + soff + (uint32_t)(tm * 2048) + offA);
            #pragma unroll
            for (int tn = 0; tn < 4; tn++)
                ldsm2(b[tn], bbase0 + soff + (uint32_t)(tn * 1024) + offB);
            #pragma unroll
            for (int tm = 0; tm < 4; tm++)
                #pragma unroll
                for (int tn = 0; tn < 4; tn++) {
                    asm volatile(
                        "mma.sync.aligned.m16n8k16.row.col.f32.f16.f16.f32 "
                        "{%0,%1,%2,%3}, {%4,%5,%6,%7}, {%8,%9}, {%0,%1,%2,%3};\n"
                        : "+f"(acc[tm][tn][0]), "+f"(acc[tm][tn][1]),
                          "+f"(acc[tm][tn][2]), "+f"(acc[tm][tn][3])
                        : "r"(a[tm][0]), "r"(a[tm][1]), "r"(a[tm][2]), "r"(a[tm][3]),
                          "r"(b[tn][0]), "r"(b[tn][1]));
                }
        }
        s  = (s  == 2) ? 0 : s + 1;
        ls = (ls == 2) ? 0 : ls + 1;
    }

    // ---- epilogue ----
    const int l4 = lane >> 2;
    const int lm = lane & 3;
    #pragma unroll
    for (int tm = 0; tm < 4; tm++) {
        const int row = m0 + wm * 64 + tm * 16 + l4;
        float f0 = alpha, f1 = alpha;
        if (MODE == 2) { f0 = alpha * rowscale[row]; f1 = alpha * rowscale[row + 8]; }
        #pragma unroll
        for (int tn = 0; tn < 4; tn++) {
            const int col = n0 + wn * 32 + tn * 8 + (lm << 1);
            if (MODE == 0) {
                const float bx = bias[col], by = bias[col + 1];
                const float v0x = acc[tm][tn][0] + bx, v0y = acc[tm][tn][1] + by;
                const float v1x = acc[tm][tn][2] + bx, v1y = acc[tm][tn][3] + by;
                if (z < 2) {
                    __half* O = (__half*)(z ? C1v : Cv);
                    *(__half2*)&O[(long long)row * KD + col] = __floats2half2_rn(v0x, v0y);
                    *(__half2*)&O[(long long)(row + 8) * KD + col] = __floats2half2_rn(v1x, v1y);
                } else {
                    __half* T = (__half*)C2v;    // [VD][MROWS]
                    T[(long long)col * MROWS + row]           = __float2half_rn(v0x);
                    T[(long long)(col + 1) * MROWS + row]     = __float2half_rn(v0y);
                    T[(long long)col * MROWS + row + 8]       = __float2half_rn(v1x);
                    T[(long long)(col + 1) * MROWS + row + 8] = __float2half_rn(v1y);
                }
            } else {
                float* O = (float*)Cv + (long long)z * sC;
                float2 v0, v1;
                v0.x = acc[tm][tn][0] * f0;
                v0.y = acc[tm][tn][1] * f0;
                v1.x = acc[tm][tn][2] * f1;
                v1.y = acc[tm][tn][3] * f1;
                *(float2*)&O[(long long)row * ldc + col]       = v0;
                *(float2*)&O[(long long)(row + 8) * ldc + col] = v1;
            }
        }
    }
}

// ---------------------------------------------------------------------------
// Prep: W[k][n] fp32 -> Wt[z][n][k] fp16
// ---------------------------------------------------------------------------
__global__ __launch_bounds__(256) void cvt_w_kernel(const float* __restrict__ Wq,
                                                    const float* __restrict__ Wk,
                                                    const float* __restrict__ Wv,
                                                    __half* __restrict__ Wt)
{
    const int i = blockIdx.x * 256 + threadIdx.x;
    if (i >= 3 * FEAT * KD) return;
    const int zz = i / (FEAT * KD);
    const int r  = (i / KD) % FEAT;      // k
    const int n  = i % KD;
    const float* W = (zz == 0) ? Wq : (zz == 1) ? Wk : Wv;
    Wt[(long long)zz * KD * FEAT + (long long)n * FEAT + r] = __float2half_rn(W[(long long)r * KD + n]);
}

// ---------------------------------------------------------------------------
// Fused: copy x into out[..., 0:FEAT] AND convert x -> fp16 (one read of x)
// ---------------------------------------------------------------------------
__global__ __launch_bounds__(256) void copy_cvt_kernel(const float4* __restrict__ x,
                                                       float4* __restrict__ out,
                                                       uint2* __restrict__ xh)
{
    const long long i = (long long)blockIdx.x * blockDim.x + threadIdx.x;
    const long long total = (long long)MROWS * (FEAT / 4);
    if (i >= total) return;
    const long long row = i / (FEAT / 4);
    const int col = (int)(i % (FEAT / 4));
    float4 v = x[i];
    out[row * (OUTD / 4) + col] = v;
    __half2 h0 = __floats2half2_rn(v.x, v.y);
    __half2 h1 = __floats2half2_rn(v.z, v.w);
    uint2 u;
    u.x = *(uint32_t*)&h0;
    u.y = *(uint32_t*)&h1;
    xh[i] = u;
}

// ---------------------------------------------------------------------------
// Warp-per-row softmax: reads fp32 logits, writes unnormalized fp16 probs
// (zeros fused in up to the 128-aligned band end); rsum = 1/sum.
// ---------------------------------------------------------------------------
__global__ __launch_bounds__(256) void softmax_kernel(const float* __restrict__ logits,
                                                      __half* __restrict__ probs,
                                                      float* __restrict__ rsum)
{
    const int wid  = threadIdx.x >> 5;
    const int lane = threadIdx.x & 31;
    const long long row = (long long)blockIdx.x * 8 + wid;
    const int q = (int)(row % SEQ);
    const float* p = logits + row * SEQ;
    __half2* o2 = (__half2*)(probs + row * SEQ);
    const int len  = q + 1;
    const int len4 = len >> 2;
    const int band2 = (((q >> 7) + 1) << 7) >> 1;   // half2 count

    float mx = -INFINITY;
    const float4* p4 = (const float4*)p;
    for (int i = lane; i < len4; i += 32) {
        float4 v = p4[i];
        mx = fmaxf(mx, fmaxf(fmaxf(v.x, v.y), fmaxf(v.z, v.w)));
    }
    for (int i = (len4 << 2) + lane; i < len; i += 32) mx = fmaxf(mx, p[i]);
    #pragma unroll
    for (int o = 16; o > 0; o >>= 1)
        mx = fmaxf(mx, __shfl_xor_sync(0xffffffffu, mx, o));

    float sum = 0.0f;
    const float2* p2 = (const float2*)p;
    for (int i = lane; i < band2; i += 32) {
        float2 v = p2[i];
        const int e0 = 2 * i, e1 = 2 * i + 1;
        float w0 = (e0 < len) ? __expf(v.x - mx) : 0.0f;
        float w1 = (e1 < len) ? __expf(v.y - mx) : 0.0f;
        sum += w0 + w1;
        o2[i] = __floats2half2_rn(w0, w1);
    }
    #pragma unroll
    for (int o = 16; o > 0; o >>= 1)
        sum += __shfl_xor_sync(0xffffffffu, sum, o);

    if (lane == 0) rsum[row] = 1.0f / sum;
}

// ---------------------------------------------------------------------------
extern "C" void kernel_launch(void* const* d_in, const int* in_sizes, int n_in,
                              void* d_out, int out_size)
{
    const float* x  = (const float*)d_in[0];
    const float* Wq = (const float*)d_in[1];
    const float* bq = (const float*)d_in[2];
    const float* Wk = (const float*)d_in[3];
    const float* bk = (const float*)d_in[4];
    const float* Wv = (const float*)d_in[5];
    const float* bv = (const float*)d_in[6];
    float* out = (float*)d_out;

    __half *xh, *wt, *qh, *kh, *vt, *ph;
    float *logits, *rsum;
    cudaGetSymbolAddress((void**)&xh,     g_xh);
    cudaGetSymbolAddress((void**)&wt,     g_wt);
    cudaGetSymbolAddress((void**)&qh,     g_qh);
    cudaGetSymbolAddress((void**)&kh,     g_kh);
    cudaGetSymbolAddress((void**)&vt,     g_vt);
    cudaGetSymbolAddress((void**)&ph,     g_ph);
    cudaGetSymbolAddress((void**)&logits, g_logits);
    cudaGetSymbolAddress((void**)&rsum,   g_rsum);

    const float scale = 0.044194173824159216f;  // 1/sqrt(512)

    cudaFuncSetAttribute(mma_gemm<0>, cudaFuncAttributeMaxDynamicSharedMemorySize, SMEM_BYTES);
    cudaFuncSetAttribute(mma_gemm<1>, cudaFuncAttributeMaxDynamicSharedMemorySize, SMEM_BYTES);
    cudaFuncSetAttribute(mma_gemm<2>, cudaFuncAttributeMaxDynamicSharedMemorySize, SMEM_BYTES);

    // prep: x copy+convert (one read), W transpose+convert
    copy_cvt_kernel<<<(int)(((long long)MROWS * (FEAT / 4) + 255) / 256), 256>>>(
        (const float4*)x, (float4*)out, (uint2*)xh);
    cvt_w_kernel<<<(3 * FEAT * KD + 255) / 256, 256>>>(Wq, Wk, Wv, wt);

    // Fused QKV projections (z: q / k / v-transposed)
    {
        dim3 grid(KD / 128, MROWS / 128, 3);
        mma_gemm<0><<<grid, 256, SMEM_BYTES>>>(
            xh, wt, bq, bk, bv, nullptr, qh, kh, vt,
            FEAT, FEAT, 0, FEAT, 0, 0, 0, 1.0f);
    }

    // logits = scale * Q @ K^T : triangular grid
    {
        dim3 grid(136, 1, BATCH);
        mma_gemm<1><<<grid, 256, SMEM_BYTES>>>(
            qh, kh, nullptr, nullptr, nullptr, nullptr, logits, nullptr, nullptr,
            KD, KD, SEQ, KD,
            (long long)SEQ * KD, (long long)SEQ * KD, (long long)SEQ * SEQ, scale);
    }

    // softmax: fp32 logits -> fp16 unnormalized probs (+band zero), 1/sum
    softmax_kernel<<<MROWS / 8, 256>>>(logits, ph, rsum);

    // read = (P @ V) * rowscale -> out[..., FEAT:]
    {
        dim3 grid(VD / 128, SEQ / 128, BATCH);
        mma_gemm<2><<<grid, 256, SMEM_BYTES>>>(
            ph, vt, nullptr, nullptr, nullptr, rsum, out + FEAT, nullptr, nullptr,
            SEQ, MROWS, OUTD, SEQ,
            (long long)SEQ * SEQ, SEQ, (long long)SEQ * OUTD, 1.0f);
    }
}

// round 12
// speedup vs baseline: 1.8958x; 1.0390x over previous
#include <cuda_runtime.h>
#include <cuda_fp16.h>
#include <math.h>
#include <stdint.h>

// Problem constants
#define BATCH 8
#define SEQ   2048
#define FEAT  1024
#define KD    512
#define VD    512
#define OUTD  1536   // FEAT + VD
#define MROWS (BATCH * SEQ)   // 16384

// Scratch (device globals; no allocations allowed)
__device__ __half g_xh[MROWS * FEAT];           // x in fp16
__device__ __half g_wt[3 * KD * FEAT];          // Wq/Wk/Wv transposed [n, k] fp16
__device__ __half g_qh[MROWS * KD];
__device__ __half g_kh[MROWS * KD];
__device__ __half g_vt[VD * MROWS];             // v transposed: [vd, b*S]
__device__ float  g_logits[BATCH * SEQ * SEQ];  // fp32 logits
__device__ __half g_ph[BATCH * SEQ * SEQ];      // unnormalized probs fp16
__device__ float  g_rsum[MROWS];                // 1/rowsum

// 3-stage smem: per stage, A = 128 rows x 32 words (16KB) + B same (16KB)
#define STAGE_WORDS 8192
#define STAGE_BYTES (STAGE_WORDS * 4)
#define SMEM_BYTES  (3 * STAGE_BYTES)           // 96 KB

__device__ __forceinline__ void cp16(uint32_t* dst, const void* src) {
    uint32_t a = (uint32_t)__cvta_generic_to_shared(dst);
    asm volatile("cp.async.cg.shared.global [%0], [%1], 16;\n" :: "r"(a), "l"(src));
}
__device__ __forceinline__ void cp_commit() {
    asm volatile("cp.async.commit_group;\n" ::: "memory");
}
__device__ __forceinline__ void cp_wait1() {
    asm volatile("cp.async.wait_group 1;\n" ::: "memory");
}
__device__ __forceinline__ void ldsm4(uint32_t* r, uint32_t addr) {
    asm volatile("ldmatrix.sync.aligned.m8n8.x4.shared.b16 {%0,%1,%2,%3}, [%4];"
        : "=r"(r[0]), "=r"(r[1]), "=r"(r[2]), "=r"(r[3]) : "r"(addr));
}
__device__ __forceinline__ void ldsm2(uint32_t* r, uint32_t addr) {
    asm volatile("ldmatrix.sync.aligned.m8n8.x2.shared.b16 {%0,%1}, [%2];"
        : "=r"(r[0]), "=r"(r[1]) : "r"(addr));
}

// ---------------------------------------------------------------------------
// fp16 tensor-core GEMM (mma m16n8k16, fp32 accum), ldmatrix fragment loads.
// CTA tile 128x128, BK=64 halfs, 3-stage cp.async, XOR-swizzled smem,
// one __syncthreads per iter, 2 CTAs/SM. A row-major [M,K], B n-major [N,K].
// MODE 0: fused QKV. z in {0,1,2}: C=qh / C1=kh / C2=vt (transposed store).
// MODE 1: QK^T -> fp32 logits * alpha. Triangular 1D grid.
// MODE 2: PV (A=probs fp16, B=vt). Causal K clamp, rowscale epilogue, fp32 out.
// ---------------------------------------------------------------------------
template<int MODE>
__global__ __launch_bounds__(256, 2) void mma_gemm(
    const __half* __restrict__ A,
    const __half* __restrict__ B,
    const float* __restrict__ bias0,
    const float* __restrict__ bias1,
    const float* __restrict__ bias2,
    const float* __restrict__ rowscale,
    void* __restrict__ Cv,
    void* __restrict__ C1v,
    void* __restrict__ C2v,
    int lda, int ldb, int ldc, int K,
    long long sA, long long sB, long long sC,
    float alpha)
{
    constexpr bool CAUSAL_K = (MODE == 2);

    int m0, n0;
    if (MODE == 1) {
        const int t = blockIdx.x;
        int i = (int)((sqrtf(8.0f * (float)t + 1.0f) - 1.0f) * 0.5f);
        if ((i + 1) * (i + 2) / 2 <= t) i++;
        if (i * (i + 1) / 2 > t) i--;
        const int j = t - i * (i + 1) / 2;
        m0 = i * 128;
        n0 = j * 128;
    } else {
        m0 = blockIdx.y * 128;
        n0 = blockIdx.x * 128;
    }

    const int z = blockIdx.z;
    const float* bias = bias0;
    if (MODE == 0) {
        B += (long long)z * KD * FEAT;          // Wt slice
        if (z == 1) bias = bias1;
        if (z == 2) bias = bias2;
    } else {
        A += (long long)z * sA;
        B += (long long)z * sB;
        if (MODE == 2) rowscale += (long long)z * SEQ;
    }

    const int K_end = CAUSAL_K ? (K < m0 + 128 ? K : m0 + 128) : K;
    const int n_iter = K_end >> 6;

    extern __shared__ uint32_t smem[];

    const int tid  = threadIdx.x;
    const int lane = tid & 31;
    const int w    = tid >> 5;
    const int wm   = w & 1;
    const int wn   = w >> 1;

    // XOR-swizzled staging: word (r,c) -> r*32 + (c ^ ((r&7)<<2)), c in [0,32)
    auto load_tile = [&](int k0, int s) {
        uint32_t* Sa = smem + s * STAGE_WORDS;
        uint32_t* Sb = Sa + 4096;
        #pragma unroll
        for (int i = 0; i < 4; i++) {
            const int idx = tid + i * 256;
            const int r   = idx >> 3;
            const int c4  = (idx & 7) << 2;            // word offset
            cp16(&Sa[r * 32 + (c4 ^ ((r & 7) << 2))],
                 &A[(long long)(m0 + r) * lda + k0 + (c4 << 1)]);
        }
        #pragma unroll
        for (int i = 0; i < 4; i++) {
            const int idx = tid + i * 256;
            const int r   = idx >> 3;
            const int c4  = (idx & 7) << 2;
            cp16(&Sb[r * 32 + (c4 ^ ((r & 7) << 2))],
                 &B[(long long)(n0 + r) * ldb + k0 + (c4 << 1)]);
        }
    };

    // ldmatrix per-lane constants
    const uint32_t sbase  = (uint32_t)__cvta_generic_to_shared(smem);
    const uint32_t maskB  = (uint32_t)((lane & 7) << 2);           // word-space swizzle mask
    const uint32_t abase0 = sbase + (uint32_t)((wm * 64 + (lane & 15)) * 128);
    const uint32_t bbase0 = sbase + 16384u + (uint32_t)((wn * 32 + (lane & 7)) * 128);
    const uint32_t cA = (uint32_t)((lane & 16) >> 2);              // 0 or 4 words
    const uint32_t cB = (uint32_t)((lane & 8) >> 1);               // 0 or 4 words

    float acc[4][4][4];
    #pragma unroll
    for (int i = 0; i < 4; i++)
        #pragma unroll
        for (int j = 0; j < 4; j++)
            #pragma unroll
            for (int r = 0; r < 4; r++) acc[i][j][r] = 0.0f;

    load_tile(0, 0);
    cp_commit();
    if (1 < n_iter) load_tile(64, 1);
    cp_commit();

    int s = 0, ls = 2;
    for (int it = 0; it < n_iter; it++) {
        cp_wait1();
        __syncthreads();

        if (it + 2 < n_iter) load_tile((it + 2) << 6, ls);
        cp_commit();

        const uint32_t soff = (uint32_t)(s * STAGE_BYTES);

        #pragma unroll
        for (int ks = 0; ks < 4; ks++) {      // 4 x k16 steps = 64 halfs
            const uint32_t kk = (uint32_t)(ks * 8);   // word offset of this step
            const uint32_t offA = ((kk + cA) ^ maskB) << 2;   // byte offset in row
            const uint32_t offB = ((kk + cB) ^ maskB) << 2;
            uint32_t a[4][4];
            uint32_t b[4][2];
            #pragma unroll
            for (int tm = 0; tm < 4; tm++)
                ldsm4(a[tm], abase0 + soff + (uint32_t)(tm * 2048) + offA);
            #pragma unroll
            for (int tn = 0; tn < 4; tn++)
                ldsm2(b[tn], bbase0 + soff + (uint32_t)(tn * 1024) + offB);
            #pragma unroll
            for (int tm = 0; tm < 4; tm++)
                #pragma unroll
                for (int tn = 0; tn < 4; tn++) {
                    asm volatile(
                        "mma.sync.aligned.m16n8k16.row.col.f32.f16.f16.f32 "
                        "{%0,%1,%2,%3}, {%4,%5,%6,%7}, {%8,%9}, {%0,%1,%2,%3};\n"
                        : "+f"(acc[tm][tn][0]), "+f"(acc[tm][tn][1]),
                          "+f"(acc[tm][tn][2]), "+f"(acc[tm][tn][3])
                        : "r"(a[tm][0]), "r"(a[tm][1]), "r"(a[tm][2]), "r"(a[tm][3]),
                          "r"(b[tn][0]), "r"(b[tn][1]));
                }
        }
        s  = (s  == 2) ? 0 : s + 1;
        ls = (ls == 2) ? 0 : ls + 1;
    }

    // ---- epilogue ----
    const int l4 = lane >> 2;
    const int lm = lane & 3;
    #pragma unroll
    for (int tm = 0; tm < 4; tm++) {
        const int row = m0 + wm * 64 + tm * 16 + l4;
        float f0 = alpha, f1 = alpha;
        if (MODE == 2) { f0 = alpha * rowscale[row]; f1 = alpha * rowscale[row + 8]; }
        #pragma unroll
        for (int tn = 0; tn < 4; tn++) {
            const int col = n0 + wn * 32 + tn * 8 + (lm << 1);
            if (MODE == 0) {
                const float bx = bias[col], by = bias[col + 1];
                const float v0x = acc[tm][tn][0] + bx, v0y = acc[tm][tn][1] + by;
                const float v1x = acc[tm][tn][2] + bx, v1y = acc[tm][tn][3] + by;
                if (z < 2) {
                    __half* O = (__half*)(z ? C1v : Cv);
                    *(__half2*)&O[(long long)row * KD + col] = __floats2half2_rn(v0x, v0y);
                    *(__half2*)&O[(long long)(row + 8) * KD + col] = __floats2half2_rn(v1x, v1y);
                } else {
                    __half* T = (__half*)C2v;    // [VD][MROWS]
                    T[(long long)col * MROWS + row]           = __float2half_rn(v0x);
                    T[(long long)(col + 1) * MROWS + row]     = __float2half_rn(v0y);
                    T[(long long)col * MROWS + row + 8]       = __float2half_rn(v1x);
                    T[(long long)(col + 1) * MROWS + row + 8] = __float2half_rn(v1y);
                }
            } else {
                float* O = (float*)Cv + (long long)z * sC;
                float2 v0, v1;
                v0.x = acc[tm][tn][0] * f0;
                v0.y = acc[tm][tn][1] * f0;
                v1.x = acc[tm][tn][2] * f1;
                v1.y = acc[tm][tn][3] * f1;
                *(float2*)&O[(long long)row * ldc + col]       = v0;
                *(float2*)&O[(long long)(row + 8) * ldc + col] = v1;
            }
        }
    }
}

// ---------------------------------------------------------------------------
// Prep: W[k][n] fp32 -> Wt[z][n][k] fp16, tiled smem transpose (coalesced R+W)
// grid: (KD/32, FEAT/32, 3), block: 32x8
// ---------------------------------------------------------------------------
__global__ __launch_bounds__(256) void cvt_w_kernel(const float* __restrict__ Wq,
                                                    const float* __restrict__ Wk,
                                                    const float* __restrict__ Wv,
                                                    __half* __restrict__ Wt)
{
    __shared__ float tile[32][33];
    const int zz = blockIdx.z;
    const float* W = (zz == 0) ? Wq : (zz == 1) ? Wk : Wv;
    __half* T = Wt + (long long)zz * KD * FEAT;

    const int n0 = blockIdx.x * 32;       // n block
    const int r0 = blockIdx.y * 32;       // k block
    const int tx = threadIdx.x;           // 0..31
    const int ty = threadIdx.y;           // 0..7

    #pragma unroll
    for (int j = 0; j < 4; j++) {
        const int r = ty + j * 8;
        tile[r][tx] = W[(long long)(r0 + r) * KD + n0 + tx];   // coalesced read
    }
    __syncthreads();
    #pragma unroll
    for (int j = 0; j < 4; j++) {
        const int n = ty + j * 8;
        T[(long long)(n0 + n) * FEAT + r0 + tx] = __float2half_rn(tile[tx][n]);  // coalesced write
    }
}

// ---------------------------------------------------------------------------
// Fused: copy x into out[..., 0:FEAT] AND convert x -> fp16 (one read of x)
// ---------------------------------------------------------------------------
__global__ __launch_bounds__(256) void copy_cvt_kernel(const float4* __restrict__ x,
                                                       float4* __restrict__ out,
                                                       uint2* __restrict__ xh)
{
    const long long i = (long long)blockIdx.x * blockDim.x + threadIdx.x;
    const long long total = (long long)MROWS * (FEAT / 4);
    if (i >= total) return;
    const long long row = i / (FEAT / 4);
    const int col = (int)(i % (FEAT / 4));
    float4 v = x[i];
    out[row * (OUTD / 4) + col] = v;
    __half2 h0 = __floats2half2_rn(v.x, v.y);
    __half2 h1 = __floats2half2_rn(v.z, v.w);
    uint2 u;
    u.x = *(uint32_t*)&h0;
    u.y = *(uint32_t*)&h1;
    xh[i] = u;
}

// ---------------------------------------------------------------------------
// Warp-per-row softmax: reads fp32 logits, writes unnormalized fp16 probs
// (zeros fused up to the 128-aligned band end); rsum = 1/sum.
// Pass 2 widened: float4 read, uint2 (2x half2) write.
// ---------------------------------------------------------------------------
__global__ __launch_bounds__(256) void softmax_kernel(const float* __restrict__ logits,
                                                      __half* __restrict__ probs,
                                                      float* __restrict__ rsum)
{
    const int wid  = threadIdx.x >> 5;
    const int lane = threadIdx.x & 31;
    const long long row = (long long)blockIdx.x * 8 + wid;
    const int q = (int)(row % SEQ);
    const float* p = logits + row * SEQ;
    uint2* o4 = (uint2*)(probs + row * SEQ);        // 4 halfs per element
    const int len  = q + 1;
    const int len4 = len >> 2;
    const int band4 = (((q >> 7) + 1) << 7) >> 2;   // groups of 4, multiple of 32

    float mx = -INFINITY;
    const float4* p4 = (const float4*)p;
    for (int i = lane; i < len4; i += 32) {
        float4 v = p4[i];
        mx = fmaxf(mx, fmaxf(fmaxf(v.x, v.y), fmaxf(v.z, v.w)));
    }
    for (int i = (len4 << 2) + lane; i < len; i += 32) mx = fmaxf(mx, p[i]);
    #pragma unroll
    for (int o = 16; o > 0; o >>= 1)
        mx = fmaxf(mx, __shfl_xor_sync(0xffffffffu, mx, o));

    float sum = 0.0f;
    for (int i = lane; i < band4; i += 32) {
        float4 v = p4[i];
        const int e = i << 2;
        float w0 = (e     < len) ? __expf(v.x - mx) : 0.0f;
        float w1 = (e + 1 < len) ? __expf(v.y - mx) : 0.0f;
        float w2 = (e + 2 < len) ? __expf(v.z - mx) : 0.0f;
        float w3 = (e + 3 < len) ? __expf(v.w - mx) : 0.0f;
        sum += (w0 + w1) + (w2 + w3);
        __half2 h0 = __floats2half2_rn(w0, w1);
        __half2 h1 = __floats2half2_rn(w2, w3);
        uint2 u;
        u.x = *(uint32_t*)&h0;
        u.y = *(uint32_t*)&h1;
        o4[i] = u;
    }
    #pragma unroll
    for (int o = 16; o > 0; o >>= 1)
        sum += __shfl_xor_sync(0xffffffffu, sum, o);

    if (lane == 0) rsum[row] = 1.0f / sum;
}

// ---------------------------------------------------------------------------
extern "C" void kernel_launch(void* const* d_in, const int* in_sizes, int n_in,
                              void* d_out, int out_size)
{
    const float* x  = (const float*)d_in[0];
    const float* Wq = (const float*)d_in[1];
    const float* bq = (const float*)d_in[2];
    const float* Wk = (const float*)d_in[3];
    const float* bk = (const float*)d_in[4];
    const float* Wv = (const float*)d_in[5];
    const float* bv = (const float*)d_in[6];
    float* out = (float*)d_out;

    __half *xh, *wt, *qh, *kh, *vt, *ph;
    float *logits, *rsum;
    cudaGetSymbolAddress((void**)&xh,     g_xh);
    cudaGetSymbolAddress((void**)&wt,     g_wt);
    cudaGetSymbolAddress((void**)&qh,     g_qh);
    cudaGetSymbolAddress((void**)&kh,     g_kh);
    cudaGetSymbolAddress((void**)&vt,     g_vt);
    cudaGetSymbolAddress((void**)&ph,     g_ph);
    cudaGetSymbolAddress((void**)&logits, g_logits);
    cudaGetSymbolAddress((void**)&rsum,   g_rsum);

    const float scale = 0.044194173824159216f;  // 1/sqrt(512)

    cudaFuncSetAttribute(mma_gemm<0>, cudaFuncAttributeMaxDynamicSharedMemorySize, SMEM_BYTES);
    cudaFuncSetAttribute(mma_gemm<1>, cudaFuncAttributeMaxDynamicSharedMemorySize, SMEM_BYTES);
    cudaFuncSetAttribute(mma_gemm<2>, cudaFuncAttributeMaxDynamicSharedMemorySize, SMEM_BYTES);

    // prep: x copy+convert (one read), W tiled transpose+convert
    copy_cvt_kernel<<<(int)(((long long)MROWS * (FEAT / 4) + 255) / 256), 256>>>(
        (const float4*)x, (float4*)out, (uint2*)xh);
    {
        dim3 grid(KD / 32, FEAT / 32, 3);
        dim3 blk(32, 8, 1);
        cvt_w_kernel<<<grid, blk>>>(Wq, Wk, Wv, wt);
    }

    // Fused QKV projections (z: q / k / v-transposed)
    {
        dim3 grid(KD / 128, MROWS / 128, 3);
        mma_gemm<0><<<grid, 256, SMEM_BYTES>>>(
            xh, wt, bq, bk, bv, nullptr, qh, kh, vt,
            FEAT, FEAT, 0, FEAT, 0, 0, 0, 1.0f);
    }

    // logits = scale * Q @ K^T : triangular grid
    {
        dim3 grid(136, 1, BATCH);
        mma_gemm<1><<<grid, 256, SMEM_BYTES>>>(
            qh, kh, nullptr, nullptr, nullptr, nullptr, logits, nullptr, nullptr,
            KD, KD, SEQ, KD,
            (long long)SEQ * KD, (long long)SEQ * KD, (long long)SEQ * SEQ, scale);
    }

    // softmax: fp32 logits -> fp16 unnormalized probs (+band zero), 1/sum
    softmax_kernel<<<MROWS / 8, 256>>>(logits, ph, rsum);

    // read = (P @ V) * rowscale -> out[..., FEAT:]
    {
        dim3 grid(VD / 128, SEQ / 128, BATCH);
        mma_gemm<2><<<grid, 256, SMEM_BYTES>>>(
            ph, vt, nullptr, nullptr, nullptr, rsum, out + FEAT, nullptr, nullptr,
            SEQ, MROWS, OUTD, SEQ,
            (long long)SEQ * SEQ, SEQ, (long long)SEQ * OUTD, 1.0f);
    }
}